// round 5
// baseline (speedup 1.0000x reference)
#include <cuda_runtime.h>
#include <math.h>

#define E 4
#define DIN 256
#define D 256
#define NB 16
#define T 1024
#define M (NB*T)            // 16384 rows per expert
#define EMD ((size_t)E*M*D) // 16,777,216 elems = 64MB fp32

// Scratch (static device globals; reuse: g_ir also holds h1, g_ii also holds h2)
__device__ float g_ir[EMD];
__device__ float g_ii[EMD];
__device__ float g_o [EMD];
__device__ float g_out[EMD];
__device__ float g_fr[E*D], g_fi[E*D], g_gam[E*D];

// ---------------- GEMM core: 128x64 block tile, BK=16, 256 threads, 8x4 micro ----
#define BM 128
#define BN 64
#define BK 16
#define BMP (BM+1)

template<int SGN>
__device__ __forceinline__ void gemm_accum(
    const float* __restrict__ A,   // M x 256 row-major
    const float* __restrict__ W,   // 256 x 256 row-major
    int m0, int n0,
    float (&acc)[8][4],
    float (&As)[BK][BMP], float (&Bs)[BK][BN], int tid)
{
    const int tx = tid & 15, ty = tid >> 4;
    for (int k0 = 0; k0 < 256; k0 += BK) {
        __syncthreads();
        // A tile 128x16 -> transposed into As[k][m]
        #pragma unroll
        for (int i = 0; i < 2; i++) {
            int idx = tid + i*256;          // 0..511 float4 slots
            int row = idx >> 2;             // 0..127
            int c4  = (idx & 3) * 4;        // 0,4,8,12
            float4 v = *(const float4*)(A + (size_t)(m0+row)*256 + k0 + c4);
            As[c4+0][row] = v.x; As[c4+1][row] = v.y;
            As[c4+2][row] = v.z; As[c4+3][row] = v.w;
        }
        // B tile 16x64
        {
            int row = tid >> 4;             // 0..15
            int c4  = (tid & 15) * 4;       // 0..60
            *(float4*)&Bs[row][c4] = *(const float4*)(W + (size_t)(k0+row)*256 + n0 + c4);
        }
        __syncthreads();
        #pragma unroll
        for (int k = 0; k < BK; k++) {
            float a[8], b[4];
            #pragma unroll
            for (int i = 0; i < 8; i++) a[i] = As[k][ty + i*16];
            #pragma unroll
            for (int j = 0; j < 4; j++) b[j] = Bs[k][tx + j*16];
            #pragma unroll
            for (int i = 0; i < 8; i++)
                #pragma unroll
                for (int j = 0; j < 4; j++) {
                    if (SGN > 0) acc[i][j] = fmaf(a[i],  b[j], acc[i][j]);
                    else         acc[i][j] = fmaf(a[i], -b[j], acc[i][j]);
                }
        }
    }
}

// ---------------- params: fr, fi, gamma ------------------------------------------
__global__ void k_params(const float* __restrict__ pl) {
    int i = blockIdx.x*blockDim.x + threadIdx.x;
    if (i < E*D) {
        float nu  = expf(pl[i]);
        float th  = expf(pl[E*D + i]);
        float gm  = expf(pl[2*E*D + i]);
        float mag = expf(-nu);
        g_fr[i]  = mag * cosf(th);
        g_fi[i]  = mag * sinf(th);
        g_gam[i] = gm;
    }
}

// ---------------- in_proj: z = k*E+e, writes gamma*u (k<2) or o ------------------
__global__ void __launch_bounds__(256) k_inproj(
    const float* __restrict__ x, const float* __restrict__ w,
    const float* __restrict__ bias)
{
    __shared__ float As[BK][BMP]; __shared__ float Bs[BK][BN];
    int m0 = blockIdx.x*BM, n0 = blockIdx.y*BN;
    int ke = blockIdx.z; int k = ke / E; int e = ke % E;
    float acc[8][4] = {};
    gemm_accum<1>(x, w + (size_t)ke*DIN*D, m0, n0, acc, As, Bs, threadIdx.x);
    int tx = threadIdx.x & 15, ty = threadIdx.x >> 4;
    float* dst = (k == 0) ? g_ir : (k == 1) ? g_ii : g_o;
    #pragma unroll
    for (int i = 0; i < 8; i++) {
        int m = m0 + ty + i*16;
        #pragma unroll
        for (int j = 0; j < 4; j++) {
            int o = n0 + tx + j*16;
            float v = acc[i][j] + bias[ke*D + o];
            if (k < 2) v *= g_gam[e*D + o];
            dst[((size_t)e*M + m)*D + o] = v;
        }
    }
}

// ---------------- LRU scan (in place on g_ir/g_ii), also emits hidden ------------
__global__ void k_scan(float* __restrict__ hid_out) {
    int i = blockIdx.x*blockDim.x + threadIdx.x;   // 0..E*NB*D-1
    int d = i % D; int b = (i / D) % NB; int e = i / (D*NB);
    float fr = g_fr[e*D+d], fi = g_fi[e*D+d];
    float hr = 0.f, hi = 0.f;
    size_t base = ((size_t)(e*NB + b)*T)*D + d;
    #pragma unroll 4
    for (int t = 0; t < T; t++) {
        size_t idx = base + (size_t)t*D;
        float ur = g_ir[idx], ui = g_ii[idx];
        float nr = fmaf(fr, hr, fmaf(-fi, hi, ur));
        float ni = fmaf(fr, hi, fmaf( fi, hr, ui));
        hr = nr; hi = ni;
        g_ir[idx] = hr; g_ii[idx] = hi;
    }
    hid_out[b*(2*E*D) + e*D + d]         = hr;
    hid_out[b*(2*E*D) + E*D + e*D + d]   = hi;
}

// ---------------- mid: out = out_r@W0 - out_i@W1 + (b0-b1) + o -------------------
__global__ void __launch_bounds__(256) k_mid(
    const float* __restrict__ mw, const float* __restrict__ mb)
{
    __shared__ float As[BK][BMP]; __shared__ float Bs[BK][BN];
    int m0 = blockIdx.x*BM, n0 = blockIdx.y*BN, e = blockIdx.z;
    float acc[8][4] = {};
    gemm_accum< 1>(g_ir + (size_t)e*M*D, mw + (size_t)e*D*D,       m0, n0, acc, As, Bs, threadIdx.x);
    gemm_accum<-1>(g_ii + (size_t)e*M*D, mw + (size_t)(E+e)*D*D,   m0, n0, acc, As, Bs, threadIdx.x);
    int tx = threadIdx.x & 15, ty = threadIdx.x >> 4;
    #pragma unroll
    for (int i = 0; i < 8; i++) {
        int m = m0 + ty + i*16;
        #pragma unroll
        for (int j = 0; j < 4; j++) {
            int o = n0 + tx + j*16;
            size_t idx = ((size_t)e*M + m)*D + o;
            g_out[idx] = acc[i][j] + mb[e*D+o] - mb[(E+e)*D+o] + g_o[idx];
        }
    }
}

// ---------------- ff1: h1 = gelu(out@W1 + b1)  (h1 -> g_ir) ----------------------
__global__ void __launch_bounds__(256) k_ff1(
    const float* __restrict__ w1, const float* __restrict__ b1)
{
    __shared__ float As[BK][BMP]; __shared__ float Bs[BK][BN];
    int m0 = blockIdx.x*BM, n0 = blockIdx.y*BN, e = blockIdx.z;
    float acc[8][4] = {};
    gemm_accum<1>(g_out + (size_t)e*M*D, w1 + (size_t)e*D*D, m0, n0, acc, As, Bs, threadIdx.x);
    int tx = threadIdx.x & 15, ty = threadIdx.x >> 4;
    #pragma unroll
    for (int i = 0; i < 8; i++) {
        int m = m0 + ty + i*16;
        #pragma unroll
        for (int j = 0; j < 4; j++) {
            int o = n0 + tx + j*16;
            float v = acc[i][j] + b1[e*D+o];
            v = 0.5f * v * (1.0f + erff(v * 0.70710678118654752f));
            g_ir[((size_t)e*M + m)*D + o] = v;
        }
    }
}

// ---------------- ff2: h2 = h1@W2 + b2 + out   (h2 -> g_ii) ----------------------
__global__ void __launch_bounds__(256) k_ff2(
    const float* __restrict__ w2, const float* __restrict__ b2)
{
    __shared__ float As[BK][BMP]; __shared__ float Bs[BK][BN];
    int m0 = blockIdx.x*BM, n0 = blockIdx.y*BN, e = blockIdx.z;
    float acc[8][4] = {};
    gemm_accum<1>(g_ir + (size_t)e*M*D, w2 + (size_t)e*D*D, m0, n0, acc, As, Bs, threadIdx.x);
    int tx = threadIdx.x & 15, ty = threadIdx.x >> 4;
    #pragma unroll
    for (int i = 0; i < 8; i++) {
        int m = m0 + ty + i*16;
        #pragma unroll
        for (int j = 0; j < 4; j++) {
            int o = n0 + tx + j*16;
            size_t idx = ((size_t)e*M + m)*D + o;
            g_ii[idx] = acc[i][j] + b2[e*D+o] + g_out[idx];
        }
    }
}

// ---------------- LayerNorm over (E,D) per (b,t) ---------------------------------
__global__ void k_ln(const float* __restrict__ lnw, const float* __restrict__ lnb,
                     float* __restrict__ out)
{
    int bt = blockIdx.x;          // 0..M-1
    int d  = threadIdx.x;         // 0..255
    float v[E]; float s = 0.f, s2 = 0.f;
    #pragma unroll
    for (int e = 0; e < E; e++) {
        float x = g_ii[((size_t)e*M + bt)*D + d];
        v[e] = x; s += x; s2 += x*x;
    }
    __shared__ float red[2][8];
    #pragma unroll
    for (int o = 16; o > 0; o >>= 1) {
        s  += __shfl_down_sync(0xffffffffu, s,  o);
        s2 += __shfl_down_sync(0xffffffffu, s2, o);
    }
    int lane = d & 31, w = d >> 5;
    if (lane == 0) { red[0][w] = s; red[1][w] = s2; }
    __syncthreads();
    if (w == 0) {
        s  = (lane < 8) ? red[0][lane] : 0.f;
        s2 = (lane < 8) ? red[1][lane] : 0.f;
        #pragma unroll
        for (int o = 4; o > 0; o >>= 1) {
            s  += __shfl_down_sync(0xffffffffu, s,  o);
            s2 += __shfl_down_sync(0xffffffffu, s2, o);
        }
        if (lane == 0) { red[0][0] = s; red[1][0] = s2; }
    }
    __syncthreads();
    float mean = red[0][0] * (1.0f/1024.0f);
    float var  = red[1][0] * (1.0f/1024.0f) - mean*mean;
    float rinv = rsqrtf(var + 1e-5f);
    #pragma unroll
    for (int e = 0; e < E; e++) {
        out[((size_t)e*M + bt)*D + d] =
            (v[e] - mean) * rinv * lnw[e*D + d] + lnb[e*D + d];
    }
}

// ---------------- launch ---------------------------------------------------------
extern "C" void kernel_launch(void* const* d_in, const int* in_sizes, int n_in,
                              void* d_out, int out_size)
{
    (void)in_sizes; (void)n_in; (void)out_size;
    const float* x   = (const float*)d_in[0];
    const float* ipw = (const float*)d_in[1];
    const float* ipb = (const float*)d_in[2];
    const float* pl  = (const float*)d_in[3];
    const float* mw  = (const float*)d_in[4];
    const float* mb  = (const float*)d_in[5];
    const float* fw1 = (const float*)d_in[6];
    const float* fb1 = (const float*)d_in[7];
    const float* fw2 = (const float*)d_in[8];
    const float* fb2 = (const float*)d_in[9];
    const float* lnw = (const float*)d_in[10];
    const float* lnb = (const float*)d_in[11];
    float* out = (float*)d_out;

    k_params<<<4, 256>>>(pl);
    dim3 gin(M/BM, D/BN, 3*E);
    k_inproj<<<gin, 256>>>(x, ipw, ipb);
    k_scan<<<(E*NB*D)/256, 256>>>(out + EMD);
    dim3 ge(M/BM, D/BN, E);
    k_mid<<<ge, 256>>>(mw, mb);
    k_ff1<<<ge, 256>>>(fw1, fb1);
    k_ff2<<<ge, 256>>>(fw2, fb2);
    k_ln<<<M, 256>>>(lnw, lnb, out);
}

// round 6
// speedup vs baseline: 2.9819x; 2.9819x over previous
#include <cuda_runtime.h>
#include <math.h>
#include <stdint.h>

#define E 4
#define DIN 256
#define D 256
#define NB 16
#define T 1024
#define M (NB*T)            // 16384 rows per expert
#define EMD ((size_t)E*M*D) // 16,777,216 elems = 64MB fp32

#define CCH 16              // scan chunks
#define CLEN (T/CCH)        // 64
#define LANES (E*NB*D)      // 8192

// Scratch (static device globals)
__device__ float g_ir[EMD];
__device__ float g_ii[EMD];
__device__ float g_o [EMD];
__device__ float g_out[EMD];
__device__ float g_fr[E*D], g_fi[E*D], g_gam[E*D];
__device__ float g_finr[LANES*CCH], g_fini[LANES*CCH];
__device__ float g_Sr[LANES*CCH],  g_Si[LANES*CCH];

// ---------------- tf32 tensor-core GEMM core -------------------------------------
// Block tile 128x64, BK=32, 256 threads = 8 warps (4 m x 2 n), warp tile 32x32.
#define BM 128
#define BN 64
#define BKK 32
#define AS_STRIDE 36   // 128x32 A tile, +4 pad (conflict-free frag loads)
#define BS_STRIDE 72   // 32x64  B tile, +8 pad

__device__ __forceinline__ uint32_t f2tf(float f) {
    uint32_t u; asm("cvt.rna.tf32.f32 %0, %1;" : "=r"(u) : "f"(f)); return u;
}

template<int SGN>
__device__ __forceinline__ void gemm_mma(
    const float* __restrict__ A,   // M x 256 row-major
    const float* __restrict__ W,   // 256 x 256 row-major
    int m0, int n0, float (&acc)[2][4][4],
    uint32_t* __restrict__ As, uint32_t* __restrict__ Bs, int tid)
{
    const int lane = tid & 31, wid = tid >> 5;
    const int g = lane >> 2, tg = lane & 3;
    const int wm0 = (wid & 3) * 32, wn0 = (wid >> 2) * 32;
    for (int k0 = 0; k0 < 256; k0 += BKK) {
        __syncthreads();
        // A tile: 128 rows x 32 cols (4 float4 per thread)
        #pragma unroll
        for (int i = 0; i < 4; i++) {
            int idx = tid + i*256;
            int row = idx >> 3, c4 = (idx & 7) * 4;
            float4 v = *(const float4*)(A + (size_t)(m0+row)*256 + k0 + c4);
            uint32_t* p = As + row*AS_STRIDE + c4;
            p[0]=f2tf(v.x); p[1]=f2tf(v.y); p[2]=f2tf(v.z); p[3]=f2tf(v.w);
        }
        // B tile: 32 rows x 64 cols (2 float4 per thread); fold SGN into B
        #pragma unroll
        for (int i = 0; i < 2; i++) {
            int idx = tid + i*256;
            int row = idx >> 4, c4 = (idx & 15) * 4;
            float4 v = *(const float4*)(W + (size_t)(k0+row)*256 + n0 + c4);
            if (SGN < 0) { v.x=-v.x; v.y=-v.y; v.z=-v.z; v.w=-v.w; }
            uint32_t* p = Bs + row*BS_STRIDE + c4;
            p[0]=f2tf(v.x); p[1]=f2tf(v.y); p[2]=f2tf(v.z); p[3]=f2tf(v.w);
        }
        __syncthreads();
        #pragma unroll
        for (int kk = 0; kk < BKK; kk += 8) {
            uint32_t a[2][4], b[4][2];
            #pragma unroll
            for (int mi = 0; mi < 2; mi++) {
                const uint32_t* base = As + (wm0 + mi*16 + g)*AS_STRIDE + kk + tg;
                a[mi][0] = base[0];
                a[mi][1] = base[8*AS_STRIDE];
                a[mi][2] = base[4];
                a[mi][3] = base[8*AS_STRIDE + 4];
            }
            #pragma unroll
            for (int ni = 0; ni < 4; ni++) {
                const uint32_t* base = Bs + (kk + tg)*BS_STRIDE + wn0 + ni*8 + g;
                b[ni][0] = base[0];
                b[ni][1] = base[4*BS_STRIDE];
            }
            #pragma unroll
            for (int mi = 0; mi < 2; mi++)
                #pragma unroll
                for (int ni = 0; ni < 4; ni++)
                    asm volatile(
                        "mma.sync.aligned.m16n8k8.row.col.f32.tf32.tf32.f32 "
                        "{%0,%1,%2,%3}, {%4,%5,%6,%7}, {%8,%9}, {%0,%1,%2,%3};"
                        : "+f"(acc[mi][ni][0]), "+f"(acc[mi][ni][1]),
                          "+f"(acc[mi][ni][2]), "+f"(acc[mi][ni][3])
                        : "r"(a[mi][0]), "r"(a[mi][1]), "r"(a[mi][2]), "r"(a[mi][3]),
                          "r"(b[ni][0]), "r"(b[ni][1]));
        }
    }
}

// ---------------- params ---------------------------------------------------------
__global__ void k_params(const float* __restrict__ pl) {
    int i = blockIdx.x*blockDim.x + threadIdx.x;
    if (i < E*D) {
        float nu  = expf(pl[i]);
        float th  = expf(pl[E*D + i]);
        float gm  = expf(pl[2*E*D + i]);
        float mag = expf(-nu);
        g_fr[i]  = mag * cosf(th);
        g_fi[i]  = mag * sinf(th);
        g_gam[i] = gm;
    }
}

// ---------------- in_proj --------------------------------------------------------
__global__ void __launch_bounds__(256) k_inproj(
    const float* __restrict__ x, const float* __restrict__ w,
    const float* __restrict__ bias)
{
    __shared__ uint32_t As[BM*AS_STRIDE];
    __shared__ uint32_t Bs[BKK*BS_STRIDE];
    int m0 = blockIdx.x*BM, n0 = blockIdx.y*BN;
    int ke = blockIdx.z; int k = ke / E; int e = ke % E;
    float acc[2][4][4] = {};
    gemm_mma<1>(x, w + (size_t)ke*DIN*D, m0, n0, acc, As, Bs, threadIdx.x);
    int lane = threadIdx.x & 31, wid = threadIdx.x >> 5;
    int g = lane >> 2, tg = lane & 3;
    int wm0 = (wid & 3) * 32, wn0 = (wid >> 2) * 32;
    float* dst = (k == 0) ? g_ir : (k == 1) ? g_ii : g_o;
    #pragma unroll
    for (int mi = 0; mi < 2; mi++) {
        int r0 = m0 + wm0 + mi*16 + g;
        #pragma unroll
        for (int ni = 0; ni < 4; ni++) {
            int c = n0 + wn0 + ni*8 + 2*tg;
            float b0 = bias[ke*D + c], b1 = bias[ke*D + c + 1];
            float s0 = (k < 2) ? g_gam[e*D + c]     : 1.0f;
            float s1 = (k < 2) ? g_gam[e*D + c + 1] : 1.0f;
            float2 v0 = make_float2((acc[mi][ni][0] + b0) * s0, (acc[mi][ni][1] + b1) * s1);
            float2 v1 = make_float2((acc[mi][ni][2] + b0) * s0, (acc[mi][ni][3] + b1) * s1);
            *(float2*)&dst[((size_t)e*M + r0    )*D + c] = v0;
            *(float2*)&dst[((size_t)e*M + r0 + 8)*D + c] = v1;
        }
    }
}

// ---------------- chunked LRU scan ----------------------------------------------
// pass 1: local scan within each chunk (h0 = 0), in place, store chunk finals
__global__ void k_scan1() {
    int i = blockIdx.x*blockDim.x + threadIdx.x;   // (eb, c, d)
    int d = i % D; int c = (i / D) % CCH; int eb = i / (D*CCH);
    int e = eb / NB;
    float fr = g_fr[e*D+d], fi = g_fi[e*D+d];
    float hr = 0.f, hi = 0.f;
    size_t idx = ((size_t)eb*T + (size_t)c*CLEN)*D + d;
    #pragma unroll 8
    for (int t = 0; t < CLEN; t++, idx += D) {
        float ur = g_ir[idx], ui = g_ii[idx];
        float nr = fmaf(fr, hr, fmaf(-fi, hi, ur));
        float ni2 = fmaf(fr, hi, fmaf( fi, hr, ui));
        hr = nr; hi = ni2;
        g_ir[idx] = hr; g_ii[idx] = hi;
    }
    g_finr[i] = hr; g_fini[i] = hi;
}

// pass 2: combine chunk finals -> global end-of-chunk states S_c; emit hidden
__global__ void k_carry(float* __restrict__ hid) {
    int i = blockIdx.x*blockDim.x + threadIdx.x;   // (eb, d)
    int d = i % D; int eb = i / D; int e = eb / NB, b = eb % NB;
    float fr = g_fr[e*D+d], fi = g_fi[e*D+d];
    float pr = fr, pi = fi;                         // f^CLEN via 6 squarings (CLEN=64)
    #pragma unroll
    for (int s = 0; s < 6; s++) { float nr = pr*pr - pi*pi, ni2 = 2.f*pr*pi; pr = nr; pi = ni2; }
    float sr = 0.f, si = 0.f;
    #pragma unroll
    for (int c = 0; c < CCH; c++) {
        int j = (eb*CCH + c)*D + d;
        float tr = pr*sr - pi*si + g_finr[j];
        float ti = pr*si + pi*sr + g_fini[j];
        sr = tr; si = ti;
        g_Sr[j] = sr; g_Si[j] = si;
    }
    hid[b*(2*E*D) + e*D + d]         = sr;
    hid[b*(2*E*D) + E*D + e*D + d]   = si;
}

// pass 3: add carried-in state contribution to chunks 1..CCH-1
__global__ void k_scan2() {
    int i = blockIdx.x*blockDim.x + threadIdx.x;
    int d = i % D; int c = (i / D) % CCH; int eb = i / (D*CCH);
    if (c == 0) return;
    int e = eb / NB;
    float fr = g_fr[e*D+d], fi = g_fi[e*D+d];
    int j = (eb*CCH + (c-1))*D + d;
    float wr = g_Sr[j], wi = g_Si[j];
    size_t idx = ((size_t)eb*T + (size_t)c*CLEN)*D + d;
    #pragma unroll 8
    for (int t = 0; t < CLEN; t++, idx += D) {
        float nr = wr*fr - wi*fi;
        float ni2 = wr*fi + wi*fr;
        wr = nr; wi = ni2;
        g_ir[idx] += wr; g_ii[idx] += wi;
    }
}

// ---------------- mid: out = out_r@W0 - out_i@W1 + (b0-b1) + o -------------------
__global__ void __launch_bounds__(256) k_mid(
    const float* __restrict__ mw, const float* __restrict__ mb)
{
    __shared__ uint32_t As[BM*AS_STRIDE];
    __shared__ uint32_t Bs[BKK*BS_STRIDE];
    int m0 = blockIdx.x*BM, n0 = blockIdx.y*BN, e = blockIdx.z;
    float acc[2][4][4] = {};
    gemm_mma< 1>(g_ir + (size_t)e*M*D, mw + (size_t)e*D*D,     m0, n0, acc, As, Bs, threadIdx.x);
    gemm_mma<-1>(g_ii + (size_t)e*M*D, mw + (size_t)(E+e)*D*D, m0, n0, acc, As, Bs, threadIdx.x);
    int lane = threadIdx.x & 31, wid = threadIdx.x >> 5;
    int g = lane >> 2, tg = lane & 3;
    int wm0 = (wid & 3) * 32, wn0 = (wid >> 2) * 32;
    #pragma unroll
    for (int mi = 0; mi < 2; mi++) {
        int r0 = m0 + wm0 + mi*16 + g;
        #pragma unroll
        for (int ni = 0; ni < 4; ni++) {
            int c = n0 + wn0 + ni*8 + 2*tg;
            float b0 = mb[e*D+c]   - mb[(E+e)*D+c];
            float b1 = mb[e*D+c+1] - mb[(E+e)*D+c+1];
            size_t i0 = ((size_t)e*M + r0    )*D + c;
            size_t i1 = ((size_t)e*M + r0 + 8)*D + c;
            float2 o0 = *(const float2*)&g_o[i0];
            float2 o1 = *(const float2*)&g_o[i1];
            *(float2*)&g_out[i0] = make_float2(acc[mi][ni][0] + b0 + o0.x, acc[mi][ni][1] + b1 + o0.y);
            *(float2*)&g_out[i1] = make_float2(acc[mi][ni][2] + b0 + o1.x, acc[mi][ni][3] + b1 + o1.y);
        }
    }
}

// ---------------- ff1: h1 = gelu(out@W1 + b1)  (h1 -> g_ir) ----------------------
__device__ __forceinline__ float gelu_f(float v) {
    return 0.5f * v * (1.0f + erff(v * 0.70710678118654752f));
}

__global__ void __launch_bounds__(256) k_ff1(
    const float* __restrict__ w1, const float* __restrict__ b1)
{
    __shared__ uint32_t As[BM*AS_STRIDE];
    __shared__ uint32_t Bs[BKK*BS_STRIDE];
    int m0 = blockIdx.x*BM, n0 = blockIdx.y*BN, e = blockIdx.z;
    float acc[2][4][4] = {};
    gemm_mma<1>(g_out + (size_t)e*M*D, w1 + (size_t)e*D*D, m0, n0, acc, As, Bs, threadIdx.x);
    int lane = threadIdx.x & 31, wid = threadIdx.x >> 5;
    int g = lane >> 2, tg = lane & 3;
    int wm0 = (wid & 3) * 32, wn0 = (wid >> 2) * 32;
    #pragma unroll
    for (int mi = 0; mi < 2; mi++) {
        int r0 = m0 + wm0 + mi*16 + g;
        #pragma unroll
        for (int ni = 0; ni < 4; ni++) {
            int c = n0 + wn0 + ni*8 + 2*tg;
            float b0 = b1[e*D+c], bb1 = b1[e*D+c+1];
            *(float2*)&g_ir[((size_t)e*M + r0    )*D + c] =
                make_float2(gelu_f(acc[mi][ni][0] + b0), gelu_f(acc[mi][ni][1] + bb1));
            *(float2*)&g_ir[((size_t)e*M + r0 + 8)*D + c] =
                make_float2(gelu_f(acc[mi][ni][2] + b0), gelu_f(acc[mi][ni][3] + bb1));
        }
    }
}

// ---------------- ff2: h2 = h1@W2 + b2 + out   (h2 -> g_ii) ----------------------
__global__ void __launch_bounds__(256) k_ff2(
    const float* __restrict__ w2, const float* __restrict__ b2)
{
    __shared__ uint32_t As[BM*AS_STRIDE];
    __shared__ uint32_t Bs[BKK*BS_STRIDE];
    int m0 = blockIdx.x*BM, n0 = blockIdx.y*BN, e = blockIdx.z;
    float acc[2][4][4] = {};
    gemm_mma<1>(g_ir + (size_t)e*M*D, w2 + (size_t)e*D*D, m0, n0, acc, As, Bs, threadIdx.x);
    int lane = threadIdx.x & 31, wid = threadIdx.x >> 5;
    int g = lane >> 2, tg = lane & 3;
    int wm0 = (wid & 3) * 32, wn0 = (wid >> 2) * 32;
    #pragma unroll
    for (int mi = 0; mi < 2; mi++) {
        int r0 = m0 + wm0 + mi*16 + g;
        #pragma unroll
        for (int ni = 0; ni < 4; ni++) {
            int c = n0 + wn0 + ni*8 + 2*tg;
            float b0 = b2[e*D+c], b1v = b2[e*D+c+1];
            size_t i0 = ((size_t)e*M + r0    )*D + c;
            size_t i1 = ((size_t)e*M + r0 + 8)*D + c;
            float2 o0 = *(const float2*)&g_out[i0];
            float2 o1 = *(const float2*)&g_out[i1];
            *(float2*)&g_ii[i0] = make_float2(acc[mi][ni][0] + b0 + o0.x, acc[mi][ni][1] + b1v + o0.y);
            *(float2*)&g_ii[i1] = make_float2(acc[mi][ni][2] + b0 + o1.x, acc[mi][ni][3] + b1v + o1.y);
        }
    }
}

// ---------------- LayerNorm over (E,D) per (b,t) ---------------------------------
__global__ void k_ln(const float* __restrict__ lnw, const float* __restrict__ lnb,
                     float* __restrict__ out)
{
    int bt = blockIdx.x;          // 0..M-1
    int d  = threadIdx.x;         // 0..255
    float v[E]; float s = 0.f, s2 = 0.f;
    #pragma unroll
    for (int e = 0; e < E; e++) {
        float x = g_ii[((size_t)e*M + bt)*D + d];
        v[e] = x; s += x; s2 += x*x;
    }
    __shared__ float red[2][8];
    #pragma unroll
    for (int o = 16; o > 0; o >>= 1) {
        s  += __shfl_down_sync(0xffffffffu, s,  o);
        s2 += __shfl_down_sync(0xffffffffu, s2, o);
    }
    int lane = d & 31, w = d >> 5;
    if (lane == 0) { red[0][w] = s; red[1][w] = s2; }
    __syncthreads();
    if (w == 0) {
        s  = (lane < 8) ? red[0][lane] : 0.f;
        s2 = (lane < 8) ? red[1][lane] : 0.f;
        #pragma unroll
        for (int o = 4; o > 0; o >>= 1) {
            s  += __shfl_down_sync(0xffffffffu, s,  o);
            s2 += __shfl_down_sync(0xffffffffu, s2, o);
        }
        if (lane == 0) { red[0][0] = s; red[1][0] = s2; }
    }
    __syncthreads();
    float mean = red[0][0] * (1.0f/1024.0f);
    float var  = red[1][0] * (1.0f/1024.0f) - mean*mean;
    float rinv = rsqrtf(var + 1e-5f);
    #pragma unroll
    for (int e = 0; e < E; e++) {
        out[((size_t)e*M + bt)*D + d] =
            (v[e] - mean) * rinv * lnw[e*D + d] + lnb[e*D + d];
    }
}

// ---------------- launch ---------------------------------------------------------
extern "C" void kernel_launch(void* const* d_in, const int* in_sizes, int n_in,
                              void* d_out, int out_size)
{
    (void)in_sizes; (void)n_in; (void)out_size;
    const float* x   = (const float*)d_in[0];
    const float* ipw = (const float*)d_in[1];
    const float* ipb = (const float*)d_in[2];
    const float* pl  = (const float*)d_in[3];
    const float* mw  = (const float*)d_in[4];
    const float* mb  = (const float*)d_in[5];
    const float* fw1 = (const float*)d_in[6];
    const float* fb1 = (const float*)d_in[7];
    const float* fw2 = (const float*)d_in[8];
    const float* fb2 = (const float*)d_in[9];
    const float* lnw = (const float*)d_in[10];
    const float* lnb = (const float*)d_in[11];
    float* out = (float*)d_out;

    k_params<<<4, 256>>>(pl);
    dim3 gin(M/BM, D/BN, 3*E);
    k_inproj<<<gin, 256>>>(x, ipw, ipb);
    k_scan1<<<(LANES*CCH)/256, 256>>>();
    k_carry<<<LANES/256, 256>>>(out + EMD);
    k_scan2<<<(LANES*CCH)/256, 256>>>();
    dim3 ge(M/BM, D/BN, E);
    k_mid<<<ge, 256>>>(mw, mb);
    k_ff1<<<ge, 256>>>(fw1, fb1);
    k_ff2<<<ge, 256>>>(fw2, fb2);
    k_ln<<<M, 256>>>(lnw, lnb, out);
}